// round 5
// baseline (speedup 1.0000x reference)
#include <cuda_runtime.h>
#include <cuda_bf16.h>

// actions: [B=4096, T=256, A=64] fp32
// out[b,0,a] = x[b,0,a]
// out[b,t,a] = out[b,t-1,a] + clip(x[b,t,a] - x[b,t-1,a], -0.5, 0.5)
//
// One thread per (b, a-quad) float4 lane; grid 512 x 128 (best measured).
// 8-timestep batch: eight named buffers, all LDG.128 issued before any
// dependent math/store. __launch_bounds__(128, 3) raises the reg ceiling so
// ptxas keeps all 8 loads in flight (R4 collapsed a 4-batch at regs=32).

#define TT   256
#define ROW4 16
#define MAXD 0.5f

__device__ __forceinline__ void step(float4& acc, float4& prev, const float4 x)
{
    acc.x += fminf(fmaxf(x.x - prev.x, -MAXD), MAXD);
    acc.y += fminf(fmaxf(x.y - prev.y, -MAXD), MAXD);
    acc.z += fminf(fmaxf(x.z - prev.z, -MAXD), MAXD);
    acc.w += fminf(fmaxf(x.w - prev.w, -MAXD), MAXD);
    prev = x;
}

__global__ __launch_bounds__(128, 3) void smooth_scan_kernel(
    const float4* __restrict__ in, float4* __restrict__ out)
{
    const unsigned idx = blockIdx.x * blockDim.x + threadIdx.x;  // 0..65535
    const unsigned b  = idx >> 4;
    const unsigned a4 = idx & 15;

    size_t base = (size_t)b * (TT * ROW4) + a4;

    float4 prev = in[base];
    float4 acc  = prev;
    out[base] = acc;

    // Peel t = 1..7 with its own front-batch.
    {
        float4 x1 = in[base + 1 * ROW4];
        float4 x2 = in[base + 2 * ROW4];
        float4 x3 = in[base + 3 * ROW4];
        float4 x4 = in[base + 4 * ROW4];
        float4 x5 = in[base + 5 * ROW4];
        float4 x6 = in[base + 6 * ROW4];
        float4 x7 = in[base + 7 * ROW4];
        step(acc, prev, x1); out[base + 1 * ROW4] = acc;
        step(acc, prev, x2); out[base + 2 * ROW4] = acc;
        step(acc, prev, x3); out[base + 3 * ROW4] = acc;
        step(acc, prev, x4); out[base + 4 * ROW4] = acc;
        step(acc, prev, x5); out[base + 5 * ROW4] = acc;
        step(acc, prev, x6); out[base + 6 * ROW4] = acc;
        step(acc, prev, x7); out[base + 7 * ROW4] = acc;
    }

    for (int t = 8; t < TT; t += 8) {
        const size_t p = base + (size_t)t * ROW4;
        // Front-batched: 8 LDG.128 independent of acc, all in flight.
        float4 x0 = in[p + 0 * ROW4];
        float4 x1 = in[p + 1 * ROW4];
        float4 x2 = in[p + 2 * ROW4];
        float4 x3 = in[p + 3 * ROW4];
        float4 x4 = in[p + 4 * ROW4];
        float4 x5 = in[p + 5 * ROW4];
        float4 x6 = in[p + 6 * ROW4];
        float4 x7 = in[p + 7 * ROW4];

        step(acc, prev, x0); out[p + 0 * ROW4] = acc;
        step(acc, prev, x1); out[p + 1 * ROW4] = acc;
        step(acc, prev, x2); out[p + 2 * ROW4] = acc;
        step(acc, prev, x3); out[p + 3 * ROW4] = acc;
        step(acc, prev, x4); out[p + 4 * ROW4] = acc;
        step(acc, prev, x5); out[p + 5 * ROW4] = acc;
        step(acc, prev, x6); out[p + 6 * ROW4] = acc;
        step(acc, prev, x7); out[p + 7 * ROW4] = acc;
    }
}

extern "C" void kernel_launch(void* const* d_in, const int* in_sizes, int n_in,
                              void* d_out, int out_size)
{
    const float4* in  = (const float4*)d_in[0];
    float4*       out = (float4*)d_out;

    const int threads = 128;
    const int blocks  = (4096 * ROW4) / threads;  // 512
    smooth_scan_kernel<<<blocks, threads>>>(in, out);
}

// round 6
// speedup vs baseline: 1.1499x; 1.1499x over previous
#include <cuda_runtime.h>
#include <cuda_bf16.h>

// actions: [B=4096, T=256, A=64] fp32
// out[b,0,a] = x[b,0,a]
// out[b,t,a] = out[b,t-1,a] + clip(x[b,t,a] - x[b,t-1,a], -0.5, 0.5)
//
// Decoupled segmented scan. CTA per batch row (4096 CTAs x 256 threads).
// Thread = (chunk c in 0..15, float4 lane a4 in 0..15); chunk = 16 timesteps.
//  Phase 1: dependency-free load of 16 float4 per thread (true MLP=16).
//  Phase 2: in-register local scan; chunk boundary x + cross-chunk exclusive
//           scan via smem (no extra global traffic).
//  Phase 3: pure streaming store of 16 float4.

#define TT     256
#define ROW4   16            // float4 lanes per (b,t) row
#define CHUNK  16            // timesteps per thread
#define NCHUNK (TT / CHUNK)  // 16
#define MAXD   0.5f

__device__ __forceinline__ float4 clip4(const float4 a, const float4 b)
{
    float4 d;
    d.x = fminf(fmaxf(a.x - b.x, -MAXD), MAXD);
    d.y = fminf(fmaxf(a.y - b.y, -MAXD), MAXD);
    d.z = fminf(fmaxf(a.z - b.z, -MAXD), MAXD);
    d.w = fminf(fmaxf(a.w - b.w, -MAXD), MAXD);
    return d;
}

__device__ __forceinline__ float4 add4(const float4 a, const float4 b)
{
    return make_float4(a.x + b.x, a.y + b.y, a.z + b.z, a.w + b.w);
}

__global__ __launch_bounds__(256, 2) void smooth_scan_kernel(
    const float4* __restrict__ in, float4* __restrict__ out)
{
    __shared__ float4 s_last[NCHUNK][ROW4];  // raw x at each chunk's last t
    __shared__ float4 s_pref[NCHUNK][ROW4];  // chunk sums -> exclusive prefixes

    const unsigned b   = blockIdx.x;
    const unsigned tid = threadIdx.x;
    const unsigned a4  = tid & 15;   // float4 lane within row
    const unsigned c   = tid >> 4;   // time chunk

    const size_t base = (size_t)b * (TT * ROW4) + (size_t)c * (CHUNK * ROW4) + a4;

    // ---- Phase 1: dependency-free streaming load ----
    float4 x[CHUNK];
    #pragma unroll
    for (int i = 0; i < CHUNK; ++i)
        x[i] = in[base + (size_t)i * ROW4];

    s_last[c][a4] = x[CHUNK - 1];
    __syncthreads();

    // ---- Phase 2a: in-place local scan (x[] becomes local scan values) ----
    // chunk 0: v[0] = x[0] (includes the base term); chunk c>0: v[0] = clipped
    // diff vs previous chunk's last raw x. v[i] = v[i-1] + clip(x[i]-x[i-1]).
    {
        float4 raw_prev = x[0];
        if (c != 0) {
            float4 xp = s_last[c - 1][a4];
            x[0] = clip4(raw_prev, xp);
        }
        #pragma unroll
        for (int i = 1; i < CHUNK; ++i) {
            float4 cur = x[i];
            x[i] = add4(x[i - 1], clip4(cur, raw_prev));
            raw_prev = cur;
        }
    }

    // ---- Phase 2b: exclusive scan of chunk sums across the 16 chunks ----
    s_pref[c][a4] = x[CHUNK - 1];
    __syncthreads();

    if (tid < ROW4) {                 // one thread per lane scans 16 chunks
        float4 run = make_float4(0.f, 0.f, 0.f, 0.f);
        #pragma unroll
        for (int cc = 0; cc < NCHUNK; ++cc) {
            float4 s = s_pref[cc][tid];
            s_pref[cc][tid] = run;
            run = add4(run, s);
        }
    }
    __syncthreads();

    const float4 P = s_pref[c][a4];

    // ---- Phase 3: streaming store ----
    #pragma unroll
    for (int i = 0; i < CHUNK; ++i)
        out[base + (size_t)i * ROW4] = add4(x[i], P);
}

extern "C" void kernel_launch(void* const* d_in, const int* in_sizes, int n_in,
                              void* d_out, int out_size)
{
    const float4* in  = (const float4*)d_in[0];
    float4*       out = (float4*)d_out;

    smooth_scan_kernel<<<4096, NCHUNK * ROW4>>>(in, out);  // 4096 x 256
}